// round 5
// baseline (speedup 1.0000x reference)
#include <cuda_runtime.h>

// ---------------- dims ----------------
#define BD 4
#define TD 16384
#define RCD 32
#define DCD 32
#define SCD 256
#define NCLS 256
#define NCOND 80
#define NLAY 40

// main kernel tiling: 512 threads (even 4 warps/SMSP), single wave (140 blocks)
#define NT1 512
#define HALO 40
#define TILE1 472
#define NTILES 35        // 35*472 = 16520 >= 16384 ; 35*4 = 140 blocks <= 148 SMs

// packed per-layer weight layout (float offsets)
// composites: FW0 = f_w@W0, FW1 = f_w@W1, GW0 = g_w@W0, GW1 = g_w@W1
#define OFF_FW0 0
#define OFF_FW1 1024
#define OFF_GW0 2048
#define OFF_GW1 3072
#define OFF_CF  4096
#define OFF_CG  6656
#define OFF_OW  9216
#define WPL     10240

// end kernel tiling
#define TT2 128

// ---------------- device scratch (static, no allocation) ----------------
__device__ float g_wpack[NLAY * WPL];       // 1.6 MB packed layer weights
__device__ float g_e1[RCD * SCD];           // e1[c*256+s] = end1_w[s*32+c]
__device__ float g_e2[SCD * NCLS];          // e2[c*256+s] = end2_w[s*256+c]
__device__ float g_skips[BD * RCD * TD];    // 8 MB skip buffer

// ---------------- f32x2 helpers ----------------
typedef unsigned long long u64;

__device__ __forceinline__ u64 pk2(float v) {
    u64 r;
    asm("mov.b64 %0, {%1, %2};" : "=l"(r) : "f"(v), "f"(v));
    return r;
}
__device__ __forceinline__ void fma2(u64 &d, u64 a, u64 b) {
    asm("fma.rn.f32x2 %0, %1, %2, %0;" : "+l"(d) : "l"(a), "l"(b));
}
__device__ __forceinline__ float2 upk(u64 v) {
    float2 r;
    asm("mov.b64 {%0, %1}, %2;" : "=f"(r.x), "=f"(r.y) : "l"(v));
    return r;
}

__device__ __forceinline__ float fast_tanh(float x) {
    float a = fminf(fmaxf(-2.f * x, -60.f), 60.f);
    float e = __expf(a);
    return (1.f - e) * __fdividef(1.f, 1.f + e);
}
__device__ __forceinline__ float fast_sig(float x) {
    float a = fminf(fmaxf(-x, -60.f), 60.f);
    float e = __expf(a);
    return __fdividef(1.f, 1.f + e);
}

// ---------------- weight repack + compose kernel ----------------
__global__ void wn_pack(const float* __restrict__ dil_w, const float* __restrict__ f_w,
                        const float* __restrict__ g_w,   const float* __restrict__ cf_w,
                        const float* __restrict__ cg_w,  const float* __restrict__ out_w,
                        const float* __restrict__ e1_w,  const float* __restrict__ e2_w) {
    int stride = gridDim.x * blockDim.x;
    int tid0 = blockIdx.x * blockDim.x + threadIdx.x;

    for (int i = tid0; i < NLAY * WPL; i += stride) {
        int l = i / WPL, off = i % WPL;
        float v;
        if (off < 4096) {
            // composite {F,G}W{0,1}[c][ch] = sum_d fg[ch][d] * dil[d][c][k]
            int which = off >> 10;                    // 0 FW0, 1 FW1, 2 GW0, 3 GW1
            int o = off & 1023;
            int c = o >> 5, ch = o & 31;
            int k = which & 1;
            const float* base = (which < 2) ? f_w : g_w;
            float s = 0.f;
            #pragma unroll 8
            for (int d = 0; d < 32; ++d)
                s += base[(l * 32 + ch) * 32 + d] * dil_w[((l * 32 + d) * 32 + c) * 2 + k];
            v = s;
        } else if (off < 6656) {                      // CF : cf_w[l][ch][c], c<80
            int o = off - 4096; int c = o >> 5, ch = o & 31;
            v = cf_w[(l * 32 + ch) * NCOND + c];
        } else if (off < 9216) {                      // CG
            int o = off - 6656; int c = o >> 5, ch = o & 31;
            v = cg_w[(l * 32 + ch) * NCOND + c];
        } else {                                      // OW : out_w[l][r][d] packed [d][r]
            int o = off - 9216; int c = o >> 5, r = o & 31;
            v = out_w[(l * 32 + r) * 32 + c];
        }
        g_wpack[i] = v;
    }
    for (int j = tid0; j < RCD * SCD; j += stride) {
        int c = j >> 8, s = j & 255;
        g_e1[j] = e1_w[s * RCD + c];
    }
    for (int j = tid0; j < SCD * NCLS; j += stride) {
        int c = j >> 8, s = j & 255;
        g_e2[j] = e2_w[s * SCD + c];
    }
}

// ---------------- fused 40-layer WaveNet body ----------------
// smem floats: res_s[32*513]=16416, fg_s[32*512]=16384, w_s[10240]  -> 172160 B
#define SM1_FLOATS (RCD * (NT1 + 1) + DCD * NT1 + WPL)
#define SM1_BYTES  (SM1_FLOATS * 4)

__global__ void __launch_bounds__(NT1, 1)
wn_main(const float* __restrict__ x, const float* __restrict__ h,
        const float* __restrict__ start_w) {
    extern __shared__ float sm[];
    float* res_s = sm;                                  // [32][NT1+1]
    float* fg_s  = res_s + RCD * (NT1 + 1);             // [32][NT1]
    float* w_s   = fg_s + DCD * NT1;                    // [WPL]

    const int tid = threadIdx.x;
    const int b = blockIdx.y;
    const int t = blockIdx.x * TILE1 - HALO + tid;
    const bool tin = (t >= 0) && (t < TD);

    if (tid < RCD) res_s[tid * (NT1 + 1)] = 0.f;        // left edge (never rewritten)

    const float xv = tin ? x[b * TD + t] : 0.f;
    float rn[RCD];                                      // running residual (skip = rn - res0)
    #pragma unroll
    for (int r = 0; r < RCD; ++r) rn[r] = start_w[r] * xv;

    for (int l = 0; l < NLAY; ++l) {
        __syncthreads();   // (A) all reads of res_s / w_s from previous layer done
        // stage this layer's packed weights
        {
            const float4* src = (const float4*)(g_wpack + l * WPL);
            float4* dst = (float4*)w_s;
            #pragma unroll
            for (int i = 0; i < WPL / 4 / NT1; ++i) dst[i * NT1 + tid] = src[i * NT1 + tid];
        }
        // publish residual column (own slot = tid+1, left neighbor reads slot tid)
        #pragma unroll
        for (int c = 0; c < RCD; ++c) res_s[c * (NT1 + 1) + tid + 1] = rn[c];
        __syncthreads();   // (B) weights + residuals visible

        // ---- two passes: pass 0 = filter (tanh), pass 1 = gate (sigmoid) ----
        #pragma unroll
        for (int pass = 0; pass < 2; ++pass) {
            u64 acc[16];                                // 32 output channels
            #pragma unroll
            for (int p = 0; p < 16; ++p) acc[p] = 0ull;

            const float* wA = w_s + (pass ? OFF_GW0 : OFF_FW0);
            const float* wB = w_s + (pass ? OFF_GW1 : OFF_FW1);
            const float* wC = w_s + (pass ? OFF_CG  : OFF_CF);

            // conv part folded: acc += WA[:,c]*res[t-1] + WB[:,c]*res[t]
            #pragma unroll 4
            for (int c = 0; c < RCD; ++c) {
                u64 vn2 = pk2(res_s[c * (NT1 + 1) + tid]);
                u64 vc2 = pk2(res_s[c * (NT1 + 1) + tid + 1]);
                const ulonglong2* a0 = (const ulonglong2*)(wA + c * 32);
                const ulonglong2* a1 = (const ulonglong2*)(wB + c * 32);
                #pragma unroll
                for (int q = 0; q < 8; ++q) {           // 8 x ulonglong2 = 32 floats
                    ulonglong2 w0 = a0[q], w1 = a1[q];
                    fma2(acc[2 * q], w0.x, vn2); fma2(acc[2 * q + 1], w0.y, vn2);
                    fma2(acc[2 * q], w1.x, vc2); fma2(acc[2 * q + 1], w1.y, vc2);
                }
            }
            // conditioning part (h from gmem; L2-resident)
            #pragma unroll 4
            for (int c = 0; c < NCOND; ++c) {
                float hv = tin ? h[(b * NCOND + c) * TD + t] : 0.f;
                u64 hv2 = pk2(hv);
                const ulonglong2* a = (const ulonglong2*)(wC + c * 32);
                #pragma unroll
                for (int q = 0; q < 8; ++q) {
                    ulonglong2 w = a[q];
                    fma2(acc[2 * q], w.x, hv2); fma2(acc[2 * q + 1], w.y, hv2);
                }
            }
            if (pass == 0) {
                #pragma unroll
                for (int p = 0; p < 16; ++p) {
                    float2 v = upk(acc[p]);
                    fg_s[(2 * p) * NT1 + tid]     = fast_tanh(v.x);
                    fg_s[(2 * p + 1) * NT1 + tid] = fast_tanh(v.y);
                }
            } else {
                #pragma unroll
                for (int p = 0; p < 16; ++p) {
                    float2 v = upk(acc[p]);
                    fg_s[(2 * p) * NT1 + tid]     *= fast_sig(v.x);
                    fg_s[(2 * p + 1) * NT1 + tid] *= fast_sig(v.y);
                }
            }
        }

        // ---- out = OW @ fg ; update residual ----
        u64 o2[16];
        #pragma unroll
        for (int p = 0; p < 16; ++p) o2[p] = 0ull;
        #pragma unroll 4
        for (int c = 0; c < DCD; ++c) {
            u64 v2 = pk2(fg_s[c * NT1 + tid]);
            const ulonglong2* a = (const ulonglong2*)(w_s + OFF_OW + c * 32);
            #pragma unroll
            for (int q = 0; q < 8; ++q) {
                ulonglong2 w = a[q];
                fma2(o2[2 * q], w.x, v2); fma2(o2[2 * q + 1], w.y, v2);
            }
        }
        #pragma unroll
        for (int p = 0; p < 16; ++p) {
            float2 o = upk(o2[p]);
            rn[2 * p]     += o.x;
            rn[2 * p + 1] += o.y;
        }
    }

    // skip = rn - res0 (res0 = start_w * xv), written for interior threads only
    if (tid >= HALO && t < TD) {
        #pragma unroll
        for (int c = 0; c < RCD; ++c)
            g_skips[(b * RCD + c) * TD + t] = rn[c] - start_w[c] * xv;
    }
}

// ---------------- end stack: relu -> 256x32 -> relu -> 256x256 ----------------
// smem: e_s[256*128]=32768, w_s[8192], s_s[32*128]=4096
#define SM2_FLOATS (SCD * TT2 + RCD * NCLS + RCD * TT2)
#define SM2_BYTES  (SM2_FLOATS * 4)

__global__ void __launch_bounds__(256, 1)
wn_end(float* __restrict__ out) {
    extern __shared__ float sm[];
    float* e_s = sm;                       // [256][TT2]
    float* w_s = e_s + SCD * TT2;          // [8192] staging (E1, then E2 chunks)
    float* s_s = w_s + RCD * NCLS;         // [32][TT2]

    const int tid = threadIdx.x;
    const int b = blockIdx.y;
    const int t0 = blockIdx.x * TT2;
    const int g = tid >> 7;                // output half (0/1)
    const int tc = tid & 127;
    const int t = t0 + tc;

    // stage E1 + relu(skips) tile
    #pragma unroll 1
    for (int i = tid; i < RCD * SCD; i += 256) w_s[i] = g_e1[i];
    #pragma unroll 1
    for (int i = tid; i < RCD * TT2; i += 256) {
        int c = i >> 7, tt = i & 127;
        s_s[i] = fmaxf(g_skips[(b * RCD + c) * TD + t0 + tt], 0.f);
    }
    __syncthreads();

    // phase A: e[128 sc half][t]
    u64 acc[64];
    #pragma unroll
    for (int p = 0; p < 64; ++p) acc[p] = 0ull;
    #pragma unroll 2
    for (int c = 0; c < RCD; ++c) {
        u64 v2 = pk2(s_s[c * TT2 + tc]);
        const ulonglong2* wr = (const ulonglong2*)(w_s + c * SCD + (g << 7));
        #pragma unroll
        for (int q = 0; q < 32; ++q) {
            ulonglong2 a = wr[q];
            fma2(acc[2 * q], a.x, v2); fma2(acc[2 * q + 1], a.y, v2);
        }
    }
    #pragma unroll
    for (int p = 0; p < 64; ++p) {
        float2 v = upk(acc[p]);
        int sc = (g << 7) + 2 * p;
        e_s[sc * TT2 + tc]       = fmaxf(v.x, 0.f);
        e_s[(sc + 1) * TT2 + tc] = fmaxf(v.y, 0.f);
    }

    // phase B: logits[128 cls half][t], E2 streamed in 8 chunks of 32 input rows
    #pragma unroll
    for (int p = 0; p < 64; ++p) acc[p] = 0ull;
    for (int kk = 0; kk < SCD / RCD; ++kk) {
        __syncthreads();   // previous w_s readers (or phase A) done; e_s visible
        #pragma unroll 1
        for (int i = tid; i < RCD * NCLS; i += 256) w_s[i] = g_e2[kk * RCD * NCLS + i];
        __syncthreads();
        #pragma unroll 2
        for (int c = 0; c < RCD; ++c) {
            u64 v2 = pk2(e_s[(kk * RCD + c) * TT2 + tc]);
            const ulonglong2* wr = (const ulonglong2*)(w_s + c * NCLS + (g << 7));
            #pragma unroll
            for (int q = 0; q < 32; ++q) {
                ulonglong2 a = wr[q];
                fma2(acc[2 * q], a.x, v2); fma2(acc[2 * q + 1], a.y, v2);
            }
        }
    }
    #pragma unroll
    for (int p = 0; p < 64; ++p) {
        float2 v = upk(acc[p]);
        int cls = (g << 7) + 2 * p;
        out[(b * NCLS + cls) * TD + t]       = v.x;
        out[(b * NCLS + cls + 1) * TD + t]   = v.y;
    }
}

// ---------------- launch ----------------
extern "C" void kernel_launch(void* const* d_in, const int* in_sizes, int n_in,
                              void* d_out, int out_size) {
    const float* x       = (const float*)d_in[0];
    const float* h       = (const float*)d_in[1];
    const float* start_w = (const float*)d_in[2];
    const float* dil_w   = (const float*)d_in[3];
    const float* f_w     = (const float*)d_in[4];
    const float* g_w     = (const float*)d_in[5];
    const float* cf_w    = (const float*)d_in[6];
    const float* cg_w    = (const float*)d_in[7];
    const float* out_w   = (const float*)d_in[8];
    const float* e1_w    = (const float*)d_in[9];
    const float* e2_w    = (const float*)d_in[10];
    float* out = (float*)d_out;

    cudaFuncSetAttribute(wn_main, cudaFuncAttributeMaxDynamicSharedMemorySize, SM1_BYTES);
    cudaFuncSetAttribute(wn_end,  cudaFuncAttributeMaxDynamicSharedMemorySize, SM2_BYTES);

    wn_pack<<<256, 256>>>(dil_w, f_w, g_w, cf_w, cg_w, out_w, e1_w, e2_w);
    wn_main<<<dim3(NTILES, BD), NT1, SM1_BYTES>>>(x, h, start_w);
    wn_end<<<dim3(TD / TT2, BD), 256, SM2_BYTES>>>(out);
}

// round 6
// speedup vs baseline: 1.7152x; 1.7152x over previous
#include <cuda_runtime.h>

// ---------------- dims ----------------
#define BD 4
#define TD 16384
#define RCD 32
#define DCD 32
#define SCD 256
#define NCLS 256
#define NCOND 80
#define NLAY 40

// main kernel tiling: 512 threads (even 4 warps/SMSP), single wave (140 blocks)
#define NT1 512
#define HALO 40
#define TILE1 472
#define NTILES 35        // 35*472 = 16520 >= 16384 ; 35*4 = 140 blocks <= 148 SMs

// packed per-layer weight layout (float offsets)
// composites: FW0 = f_w@W0, FW1 = f_w@W1, GW0 = g_w@W0, GW1 = g_w@W1
#define OFF_FW0 0
#define OFF_FW1 1024
#define OFF_GW0 2048
#define OFF_GW1 3072
#define OFF_CF  4096
#define OFF_CG  6656
#define OFF_OW  9216
#define WPL     10240

// end kernel tiling
#define TT2 128

// ---------------- device scratch (static, no allocation) ----------------
__device__ float g_wpack[NLAY * WPL];       // 1.6 MB packed layer weights
__device__ float g_e1[RCD * SCD];           // e1[c*256+s] = end1_w[s*32+c]
__device__ float g_e2[SCD * NCLS];          // e2[c*256+s] = end2_w[s*256+c]
__device__ float g_skips[BD * RCD * TD];    // 8 MB skip buffer

// ---------------- f32x2 helpers ----------------
typedef unsigned long long u64;

__device__ __forceinline__ u64 pk2(float v) {
    u64 r;
    asm("mov.b64 %0, {%1, %2};" : "=l"(r) : "f"(v), "f"(v));
    return r;
}
__device__ __forceinline__ void fma2(u64 &d, u64 a, u64 b) {
    asm("fma.rn.f32x2 %0, %1, %2, %0;" : "+l"(d) : "l"(a), "l"(b));
}
__device__ __forceinline__ float2 upk(u64 v) {
    float2 r;
    asm("mov.b64 {%0, %1}, %2;" : "=f"(r.x), "=f"(r.y) : "l"(v));
    return r;
}

__device__ __forceinline__ float fast_tanh(float x) {
    float a = fminf(fmaxf(-2.f * x, -60.f), 60.f);
    float e = __expf(a);
    return (1.f - e) * __fdividef(1.f, 1.f + e);
}
__device__ __forceinline__ float fast_sig(float x) {
    float a = fminf(fmaxf(-x, -60.f), 60.f);
    float e = __expf(a);
    return __fdividef(1.f, 1.f + e);
}

// ---------------- weight repack + compose kernel ----------------
__global__ void wn_pack(const float* __restrict__ dil_w, const float* __restrict__ f_w,
                        const float* __restrict__ g_w,   const float* __restrict__ cf_w,
                        const float* __restrict__ cg_w,  const float* __restrict__ out_w,
                        const float* __restrict__ e1_w,  const float* __restrict__ e2_w) {
    int stride = gridDim.x * blockDim.x;
    int tid0 = blockIdx.x * blockDim.x + threadIdx.x;

    for (int i = tid0; i < NLAY * WPL; i += stride) {
        int l = i / WPL, off = i % WPL;
        float v;
        if (off < 4096) {
            // composite {F,G}W{0,1}[c][ch] = sum_d fg[ch][d] * dil[d][c][k]
            int which = off >> 10;                    // 0 FW0, 1 FW1, 2 GW0, 3 GW1
            int o = off & 1023;
            int c = o >> 5, ch = o & 31;
            int k = which & 1;
            const float* base = (which < 2) ? f_w : g_w;
            float s = 0.f;
            #pragma unroll 8
            for (int d = 0; d < 32; ++d)
                s += base[(l * 32 + ch) * 32 + d] * dil_w[((l * 32 + d) * 32 + c) * 2 + k];
            v = s;
        } else if (off < 6656) {                      // CF : cf_w[l][ch][c], c<80
            int o = off - 4096; int c = o >> 5, ch = o & 31;
            v = cf_w[(l * 32 + ch) * NCOND + c];
        } else if (off < 9216) {                      // CG
            int o = off - 6656; int c = o >> 5, ch = o & 31;
            v = cg_w[(l * 32 + ch) * NCOND + c];
        } else {                                      // OW : out_w[l][r][d] packed [d][r]
            int o = off - 9216; int c = o >> 5, r = o & 31;
            v = out_w[(l * 32 + r) * 32 + c];
        }
        g_wpack[i] = v;
    }
    for (int j = tid0; j < RCD * SCD; j += stride) {
        int c = j >> 8, s = j & 255;
        g_e1[j] = e1_w[s * RCD + c];
    }
    for (int j = tid0; j < SCD * NCLS; j += stride) {
        int c = j >> 8, s = j & 255;
        g_e2[j] = e2_w[s * SCD + c];
    }
}

// ---------------- fused 40-layer WaveNet body ----------------
// smem floats: res_s[32*513]=16416, fg_s[32*512]=16384, w_s[10240]  -> 172160 B
#define SM1_FLOATS (RCD * (NT1 + 1) + DCD * NT1 + WPL)
#define SM1_BYTES  (SM1_FLOATS * 4)

__global__ void __launch_bounds__(NT1, 1)
wn_main(const float* __restrict__ x, const float* __restrict__ h,
        const float* __restrict__ start_w) {
    extern __shared__ float sm[];
    float* res_s = sm;                                  // [32][NT1+1]
    float* fg_s  = res_s + RCD * (NT1 + 1);             // [32][NT1]
    float* w_s   = fg_s + DCD * NT1;                    // [WPL]

    const int tid = threadIdx.x;
    const int b = blockIdx.y;
    const int t = blockIdx.x * TILE1 - HALO + tid;
    const bool tin = (t >= 0) && (t < TD);

    if (tid < RCD) res_s[tid * (NT1 + 1)] = 0.f;        // left edge: frozen 0 (halo absorbs)

    const float xv = tin ? x[b * TD + t] : 0.f;
    // residual lives ONLY in smem (no rn[] registers): init to start conv
    #pragma unroll
    for (int c = 0; c < RCD; ++c)
        res_s[c * (NT1 + 1) + tid + 1] = start_w[c] * xv;

    for (int l = 0; l < NLAY; ++l) {
        __syncthreads();   // (A) all res_s updates + prior w_s reads complete
        // stage this layer's packed weights
        {
            const float4* src = (const float4*)(g_wpack + l * WPL);
            float4* dst = (float4*)w_s;
            #pragma unroll
            for (int i = 0; i < WPL / 4 / NT1; ++i) dst[i * NT1 + tid] = src[i * NT1 + tid];
        }
        __syncthreads();   // (B) weights + residuals visible

        // ---- two passes, strictly serialized (register pressure control) ----
        #pragma unroll 1
        for (int pass = 0; pass < 2; ++pass) {
            u64 acc[16];                                // 32 output channels
            #pragma unroll
            for (int p = 0; p < 16; ++p) acc[p] = 0ull;

            const float* wA = w_s + (pass ? OFF_GW0 : OFF_FW0);
            const float* wB = w_s + (pass ? OFF_GW1 : OFF_FW1);
            const float* wC = w_s + (pass ? OFF_CG  : OFF_CF);

            // conv part folded: acc += WA[:,c]*res[t-1] + WB[:,c]*res[t]
            #pragma unroll 4
            for (int c = 0; c < RCD; ++c) {
                u64 vn2 = pk2(res_s[c * (NT1 + 1) + tid]);
                u64 vc2 = pk2(res_s[c * (NT1 + 1) + tid + 1]);
                const ulonglong2* a0 = (const ulonglong2*)(wA + c * 32);
                const ulonglong2* a1 = (const ulonglong2*)(wB + c * 32);
                #pragma unroll
                for (int q = 0; q < 8; ++q) {           // 8 x ulonglong2 = 32 floats
                    ulonglong2 w0 = a0[q], w1 = a1[q];
                    fma2(acc[2 * q], w0.x, vn2); fma2(acc[2 * q + 1], w0.y, vn2);
                    fma2(acc[2 * q], w1.x, vc2); fma2(acc[2 * q + 1], w1.y, vc2);
                }
            }
            // conditioning part (h from gmem; L2-resident)
            #pragma unroll 4
            for (int c = 0; c < NCOND; ++c) {
                float hv = tin ? h[(b * NCOND + c) * TD + t] : 0.f;
                u64 hv2 = pk2(hv);
                const ulonglong2* a = (const ulonglong2*)(wC + c * 32);
                #pragma unroll
                for (int q = 0; q < 8; ++q) {
                    ulonglong2 w = a[q];
                    fma2(acc[2 * q], w.x, hv2); fma2(acc[2 * q + 1], w.y, hv2);
                }
            }
            if (pass == 0) {
                #pragma unroll
                for (int p = 0; p < 16; ++p) {
                    float2 v = upk(acc[p]);
                    fg_s[(2 * p) * NT1 + tid]     = fast_tanh(v.x);
                    fg_s[(2 * p + 1) * NT1 + tid] = fast_tanh(v.y);
                }
            } else {
                #pragma unroll
                for (int p = 0; p < 16; ++p) {
                    float2 v = upk(acc[p]);
                    fg_s[(2 * p) * NT1 + tid]     *= fast_sig(v.x);
                    fg_s[(2 * p + 1) * NT1 + tid] *= fast_sig(v.y);
                }
            }
        }

        __syncthreads();   // (C) all res_s reads for this layer complete before update

        // ---- out = OW @ fg ; update residual in place (own slot only) ----
        u64 o2[16];
        #pragma unroll
        for (int p = 0; p < 16; ++p) o2[p] = 0ull;
        #pragma unroll 4
        for (int c = 0; c < DCD; ++c) {
            u64 v2 = pk2(fg_s[c * NT1 + tid]);
            const ulonglong2* a = (const ulonglong2*)(w_s + OFF_OW + c * 32);
            #pragma unroll
            for (int q = 0; q < 8; ++q) {
                ulonglong2 w = a[q];
                fma2(o2[2 * q], w.x, v2); fma2(o2[2 * q + 1], w.y, v2);
            }
        }
        #pragma unroll
        for (int p = 0; p < 16; ++p) {
            float2 o = upk(o2[p]);
            res_s[(2 * p) * (NT1 + 1) + tid + 1]     += o.x;
            res_s[(2 * p + 1) * (NT1 + 1) + tid + 1] += o.y;
        }
    }

    // skip = res_final - res0 (res0 = start_w * xv); interior threads only
    if (tid >= HALO && t < TD) {
        #pragma unroll
        for (int c = 0; c < RCD; ++c)
            g_skips[(b * RCD + c) * TD + t] =
                res_s[c * (NT1 + 1) + tid + 1] - start_w[c] * xv;
    }
}

// ---------------- end stack: relu -> 256x32 -> relu -> 256x256 ----------------
// smem: e_s[256*128]=32768, w_s[8192], s_s[32*128]=4096
#define SM2_FLOATS (SCD * TT2 + RCD * NCLS + RCD * TT2)
#define SM2_BYTES  (SM2_FLOATS * 4)

__global__ void __launch_bounds__(256, 1)
wn_end(float* __restrict__ out) {
    extern __shared__ float sm[];
    float* e_s = sm;                       // [256][TT2]
    float* w_s = e_s + SCD * TT2;          // [8192] staging (E1, then E2 chunks)
    float* s_s = w_s + RCD * NCLS;         // [32][TT2]

    const int tid = threadIdx.x;
    const int b = blockIdx.y;
    const int t0 = blockIdx.x * TT2;
    const int g = tid >> 7;                // output half (0/1)
    const int tc = tid & 127;
    const int t = t0 + tc;

    // stage E1 + relu(skips) tile
    #pragma unroll 1
    for (int i = tid; i < RCD * SCD; i += 256) w_s[i] = g_e1[i];
    #pragma unroll 1
    for (int i = tid; i < RCD * TT2; i += 256) {
        int c = i >> 7, tt = i & 127;
        s_s[i] = fmaxf(g_skips[(b * RCD + c) * TD + t0 + tt], 0.f);
    }
    __syncthreads();

    // phase A: e[128 sc half][t]
    u64 acc[64];
    #pragma unroll
    for (int p = 0; p < 64; ++p) acc[p] = 0ull;
    #pragma unroll 2
    for (int c = 0; c < RCD; ++c) {
        u64 v2 = pk2(s_s[c * TT2 + tc]);
        const ulonglong2* wr = (const ulonglong2*)(w_s + c * SCD + (g << 7));
        #pragma unroll
        for (int q = 0; q < 32; ++q) {
            ulonglong2 a = wr[q];
            fma2(acc[2 * q], a.x, v2); fma2(acc[2 * q + 1], a.y, v2);
        }
    }
    #pragma unroll
    for (int p = 0; p < 64; ++p) {
        float2 v = upk(acc[p]);
        int sc = (g << 7) + 2 * p;
        e_s[sc * TT2 + tc]       = fmaxf(v.x, 0.f);
        e_s[(sc + 1) * TT2 + tc] = fmaxf(v.y, 0.f);
    }

    // phase B: logits[128 cls half][t], E2 streamed in 8 chunks of 32 input rows
    #pragma unroll
    for (int p = 0; p < 64; ++p) acc[p] = 0ull;
    for (int kk = 0; kk < SCD / RCD; ++kk) {
        __syncthreads();   // previous w_s readers (or phase A) done; e_s visible
        #pragma unroll 1
        for (int i = tid; i < RCD * NCLS; i += 256) w_s[i] = g_e2[kk * RCD * NCLS + i];
        __syncthreads();
        #pragma unroll 2
        for (int c = 0; c < RCD; ++c) {
            u64 v2 = pk2(e_s[(kk * RCD + c) * TT2 + tc]);
            const ulonglong2* wr = (const ulonglong2*)(w_s + c * NCLS + (g << 7));
            #pragma unroll
            for (int q = 0; q < 32; ++q) {
                ulonglong2 a = wr[q];
                fma2(acc[2 * q], a.x, v2); fma2(acc[2 * q + 1], a.y, v2);
            }
        }
    }
    #pragma unroll
    for (int p = 0; p < 64; ++p) {
        float2 v = upk(acc[p]);
        int cls = (g << 7) + 2 * p;
        out[(b * NCLS + cls) * TD + t]       = v.x;
        out[(b * NCLS + cls + 1) * TD + t]   = v.y;
    }
}

// ---------------- launch ----------------
extern "C" void kernel_launch(void* const* d_in, const int* in_sizes, int n_in,
                              void* d_out, int out_size) {
    const float* x       = (const float*)d_in[0];
    const float* h       = (const float*)d_in[1];
    const float* start_w = (const float*)d_in[2];
    const float* dil_w   = (const float*)d_in[3];
    const float* f_w     = (const float*)d_in[4];
    const float* g_w     = (const float*)d_in[5];
    const float* cf_w    = (const float*)d_in[6];
    const float* cg_w    = (const float*)d_in[7];
    const float* out_w   = (const float*)d_in[8];
    const float* e1_w    = (const float*)d_in[9];
    const float* e2_w    = (const float*)d_in[10];
    float* out = (float*)d_out;

    cudaFuncSetAttribute(wn_main, cudaFuncAttributeMaxDynamicSharedMemorySize, SM1_BYTES);
    cudaFuncSetAttribute(wn_end,  cudaFuncAttributeMaxDynamicSharedMemorySize, SM2_BYTES);

    wn_pack<<<256, 256>>>(dil_w, f_w, g_w, cf_w, cg_w, out_w, e1_w, e2_w);
    wn_main<<<dim3(NTILES, BD), NT1, SM1_BYTES>>>(x, h, start_w);
    wn_end<<<dim3(TD / TT2, BD), 256, SM2_BYTES>>>(out);
}

// round 7
// speedup vs baseline: 1.8952x; 1.1050x over previous
#include <cuda_runtime.h>

// ---------------- dims ----------------
#define BD 4
#define TD 16384
#define RCD 32
#define DCD 32
#define SCD 256
#define NCLS 256
#define NCOND 80
#define NLAY 40

// main kernel tiling: 512 threads, single wave (140 blocks)
#define NT1 512
#define HALO 40
#define TILE1 472
#define NTILES 35        // 35*472 = 16520 >= 16384 ; 35*4 = 140 blocks <= 148 SMs

// packed per-layer weight layout (float offsets)
#define OFF_FW0 0
#define OFF_FW1 1024
#define OFF_GW0 2048
#define OFF_GW1 3072
#define OFF_CF  4096
#define OFF_CG  6656
#define OFF_OW  9216
#define WPL     10240

// end kernel tiling
#define TT2 128
#define NT2 512

// ---------------- device scratch (static, no allocation) ----------------
__device__ float g_wpack[NLAY * WPL];       // 1.6 MB packed layer weights
__device__ float g_e1[RCD * SCD];           // e1[c*256+s] = end1_w[s*32+c]
__device__ float g_e2[SCD * NCLS];          // e2[c*256+s] = end2_w[s*256+c]
__device__ float g_skips[BD * RCD * TD];    // 8 MB skip buffer

// ---------------- f32x2 helpers ----------------
typedef unsigned long long u64;

__device__ __forceinline__ u64 pk2(float v) {
    u64 r;
    asm("mov.b64 %0, {%1, %2};" : "=l"(r) : "f"(v), "f"(v));
    return r;
}
__device__ __forceinline__ void fma2(u64 &d, u64 a, u64 b) {
    asm("fma.rn.f32x2 %0, %1, %2, %0;" : "+l"(d) : "l"(a), "l"(b));
}
__device__ __forceinline__ float2 upk(u64 v) {
    float2 r;
    asm("mov.b64 {%0, %1}, %2;" : "=f"(r.x), "=f"(r.y) : "l"(v));
    return r;
}

__device__ __forceinline__ float fast_tanh(float x) {
    float a = fminf(fmaxf(-2.f * x, -60.f), 60.f);
    float e = __expf(a);
    return (1.f - e) * __fdividef(1.f, 1.f + e);
}
__device__ __forceinline__ float fast_sig(float x) {
    float a = fminf(fmaxf(-x, -60.f), 60.f);
    float e = __expf(a);
    return __fdividef(1.f, 1.f + e);
}

// ---------------- weight repack + compose kernel ----------------
__global__ void wn_pack(const float* __restrict__ dil_w, const float* __restrict__ f_w,
                        const float* __restrict__ g_w,   const float* __restrict__ cf_w,
                        const float* __restrict__ cg_w,  const float* __restrict__ out_w,
                        const float* __restrict__ e1_w,  const float* __restrict__ e2_w) {
    int stride = gridDim.x * blockDim.x;
    int tid0 = blockIdx.x * blockDim.x + threadIdx.x;

    for (int i = tid0; i < NLAY * WPL; i += stride) {
        int l = i / WPL, off = i % WPL;
        float v;
        if (off < 4096) {
            // composite {F,G}W{0,1}[c][ch] = sum_d fg[ch][d] * dil[d][c][k]
            int which = off >> 10;                    // 0 FW0, 1 FW1, 2 GW0, 3 GW1
            int o = off & 1023;
            int c = o >> 5, ch = o & 31;
            int k = which & 1;
            const float* base = (which < 2) ? f_w : g_w;
            float s = 0.f;
            #pragma unroll 8
            for (int d = 0; d < 32; ++d)
                s += base[(l * 32 + ch) * 32 + d] * dil_w[((l * 32 + d) * 32 + c) * 2 + k];
            v = s;
        } else if (off < 6656) {                      // CF : cf_w[l][ch][c], c<80
            int o = off - 4096; int c = o >> 5, ch = o & 31;
            v = cf_w[(l * 32 + ch) * NCOND + c];
        } else if (off < 9216) {                      // CG
            int o = off - 6656; int c = o >> 5, ch = o & 31;
            v = cg_w[(l * 32 + ch) * NCOND + c];
        } else {                                      // OW : out_w[l][r][d] packed [d][r]
            int o = off - 9216; int c = o >> 5, r = o & 31;
            v = out_w[(l * 32 + r) * 32 + c];
        }
        g_wpack[i] = v;
    }
    for (int j = tid0; j < RCD * SCD; j += stride) {
        int c = j >> 8, s = j & 255;
        g_e1[j] = e1_w[s * RCD + c];
    }
    for (int j = tid0; j < SCD * NCLS; j += stride) {
        int c = j >> 8, s = j & 255;
        g_e2[j] = e2_w[s * SCD + c];
    }
}

// ---------------- fused 40-layer WaveNet body ----------------
// smem: res double buffer 2*32*513 + weight double buffer 2*10240 = 53312 fl = 208.3KB
#define SM1_FLOATS (2 * RCD * (NT1 + 1) + 2 * WPL)
#define SM1_BYTES  (SM1_FLOATS * 4)

__global__ void __launch_bounds__(NT1, 1)
wn_main(const float* __restrict__ x, const float* __restrict__ h,
        const float* __restrict__ start_w) {
    extern __shared__ float sm[];
    float* res0 = sm;                                   // [32][NT1+1]
    float* res1 = res0 + RCD * (NT1 + 1);
    float* w0s  = res1 + RCD * (NT1 + 1);               // [WPL]
    float* w1s  = w0s + WPL;

    const int tid = threadIdx.x;
    const int b = blockIdx.y;
    const int t = blockIdx.x * TILE1 - HALO + tid;
    const bool tin = (t >= 0) && (t < TD);

    if (tid < RCD) {                                    // frozen left edges (both buffers)
        res0[tid * (NT1 + 1)] = 0.f;
        res1[tid * (NT1 + 1)] = 0.f;
    }

    const float xv = tin ? x[b * TD + t] : 0.f;
    #pragma unroll
    for (int c = 0; c < RCD; ++c)
        res0[c * (NT1 + 1) + tid + 1] = start_w[c] * xv;

    // prologue: stage layer-0 weights
    {
        const float4* src = (const float4*)g_wpack;
        float4* dst = (float4*)w0s;
        #pragma unroll
        for (int i = 0; i < WPL / 4 / NT1; ++i) dst[i * NT1 + tid] = src[i * NT1 + tid];
    }

    const float* hb = h + b * NCOND * TD + t;           // column base (valid only if tin)

    for (int l = 0; l < NLAY; ++l) {
        __syncthreads();   // the ONLY barrier per layer

        const int cur = l & 1;
        const float* rc = cur ? res1 : res0;
        float*       rn = cur ? res0 : res1;
        const float* wc = cur ? w1s  : w0s;
        float*       wp = cur ? w0s  : w1s;

        // prefetch next layer's weights into the idle buffer (read next iter, after sync)
        if (l + 1 < NLAY) {
            const float4* src = (const float4*)(g_wpack + (l + 1) * WPL);
            float4* dst = (float4*)wp;
            #pragma unroll
            for (int i = 0; i < WPL / 4 / NT1; ++i) dst[i * NT1 + tid] = src[i * NT1 + tid];
        }

        // ---- merged conditioning: one h load feeds filter AND gate ----
        u64 f2[16], g2[16];
        #pragma unroll
        for (int p = 0; p < 16; ++p) { f2[p] = 0ull; g2[p] = 0ull; }

        #pragma unroll 4
        for (int c = 0; c < NCOND; ++c) {
            float hv = tin ? hb[c * TD] : 0.f;
            u64 hv2 = pk2(hv);
            const ulonglong2* cf = (const ulonglong2*)(wc + OFF_CF + c * 32);
            const ulonglong2* cg = (const ulonglong2*)(wc + OFF_CG + c * 32);
            #pragma unroll
            for (int q = 0; q < 8; ++q) {
                ulonglong2 wf = cf[q];
                fma2(f2[2 * q], wf.x, hv2); fma2(f2[2 * q + 1], wf.y, hv2);
                ulonglong2 wg = cg[q];
                fma2(g2[2 * q], wg.x, hv2); fma2(g2[2 * q + 1], wg.y, hv2);
            }
        }

        // ---- conv (folded) filter part ----
        #pragma unroll 4
        for (int c = 0; c < RCD; ++c) {
            u64 vn2 = pk2(rc[c * (NT1 + 1) + tid]);
            u64 vc2 = pk2(rc[c * (NT1 + 1) + tid + 1]);
            const ulonglong2* a0 = (const ulonglong2*)(wc + OFF_FW0 + c * 32);
            const ulonglong2* a1 = (const ulonglong2*)(wc + OFF_FW1 + c * 32);
            #pragma unroll
            for (int q = 0; q < 8; ++q) {
                ulonglong2 w0 = a0[q], w1 = a1[q];
                fma2(f2[2 * q], w0.x, vn2); fma2(f2[2 * q + 1], w0.y, vn2);
                fma2(f2[2 * q], w1.x, vc2); fma2(f2[2 * q + 1], w1.y, vc2);
            }
        }
        float filt[32];
        #pragma unroll
        for (int p = 0; p < 16; ++p) {
            float2 v = upk(f2[p]);
            filt[2 * p]     = fast_tanh(v.x);
            filt[2 * p + 1] = fast_tanh(v.y);
        }

        // ---- conv (folded) gate part ----
        #pragma unroll 4
        for (int c = 0; c < RCD; ++c) {
            u64 vn2 = pk2(rc[c * (NT1 + 1) + tid]);
            u64 vc2 = pk2(rc[c * (NT1 + 1) + tid + 1]);
            const ulonglong2* a0 = (const ulonglong2*)(wc + OFF_GW0 + c * 32);
            const ulonglong2* a1 = (const ulonglong2*)(wc + OFF_GW1 + c * 32);
            #pragma unroll
            for (int q = 0; q < 8; ++q) {
                ulonglong2 w0 = a0[q], w1 = a1[q];
                fma2(g2[2 * q], w0.x, vn2); fma2(g2[2 * q + 1], w0.y, vn2);
                fma2(g2[2 * q], w1.x, vc2); fma2(g2[2 * q + 1], w1.y, vc2);
            }
        }
        #pragma unroll
        for (int p = 0; p < 16; ++p) {
            float2 v = upk(g2[p]);
            filt[2 * p]     *= fast_sig(v.x);
            filt[2 * p + 1] *= fast_sig(v.y);
        }

        // ---- out = OW @ fg (register source: FULL unroll) ; residual -> next buffer ----
        u64 o2[16];
        #pragma unroll
        for (int p = 0; p < 16; ++p) o2[p] = 0ull;
        #pragma unroll
        for (int c = 0; c < DCD; ++c) {
            u64 v2 = pk2(filt[c]);
            const ulonglong2* a = (const ulonglong2*)(wc + OFF_OW + c * 32);
            #pragma unroll
            for (int q = 0; q < 8; ++q) {
                ulonglong2 w = a[q];
                fma2(o2[2 * q], w.x, v2); fma2(o2[2 * q + 1], w.y, v2);
            }
        }
        #pragma unroll
        for (int p = 0; p < 16; ++p) {
            float2 o = upk(o2[p]);
            rn[(2 * p) * (NT1 + 1) + tid + 1]     = rc[(2 * p) * (NT1 + 1) + tid + 1] + o.x;
            rn[(2 * p + 1) * (NT1 + 1) + tid + 1] = rc[(2 * p + 1) * (NT1 + 1) + tid + 1] + o.y;
        }
    }

    // l=39 wrote res0. skip = res_final - res0_init; own slot only -> no barrier needed.
    if (tid >= HALO && t < TD) {
        #pragma unroll
        for (int c = 0; c < RCD; ++c)
            g_skips[(b * RCD + c) * TD + t] =
                res0[c * (NT1 + 1) + tid + 1] - start_w[c] * xv;
    }
}

// ---------------- end stack: relu -> 256x32 -> relu -> 256x256 ----------------
// 512 threads: tc = tid&127 (time), g = tid>>7 (quarter of outputs, 64 each)
// smem: e_s[256*128]=32768, w_s[8192], s_s[32*128]=4096  -> 176KB
#define SM2_FLOATS (SCD * TT2 + RCD * NCLS + RCD * TT2)
#define SM2_BYTES  (SM2_FLOATS * 4)

__global__ void __launch_bounds__(NT2, 1)
wn_end(float* __restrict__ out) {
    extern __shared__ float sm[];
    float* e_s = sm;                       // [256][TT2]
    float* w_s = e_s + SCD * TT2;          // [8192] staging (E1, then E2 chunks)
    float* s_s = w_s + RCD * NCLS;         // [32][TT2]

    const int tid = threadIdx.x;
    const int b = blockIdx.y;
    const int t0 = blockIdx.x * TT2;
    const int g = tid >> 7;                // output quarter (0..3), 64 outputs
    const int tc = tid & 127;
    const int t = t0 + tc;

    // stage E1 + relu(skips) tile
    #pragma unroll 1
    for (int i = tid; i < RCD * SCD; i += NT2) w_s[i] = g_e1[i];
    #pragma unroll 1
    for (int i = tid; i < RCD * TT2; i += NT2) {
        int c = i >> 7, tt = i & 127;
        s_s[i] = fmaxf(g_skips[(b * RCD + c) * TD + t0 + tt], 0.f);
    }
    __syncthreads();

    // phase A: e[g*64 .. g*64+63][tc]
    u64 acc[32];
    #pragma unroll
    for (int p = 0; p < 32; ++p) acc[p] = 0ull;
    #pragma unroll 2
    for (int c = 0; c < RCD; ++c) {
        u64 v2 = pk2(s_s[c * TT2 + tc]);
        const ulonglong2* wr = (const ulonglong2*)(w_s + c * SCD + (g << 6));
        #pragma unroll
        for (int q = 0; q < 16; ++q) {
            ulonglong2 a = wr[q];
            fma2(acc[2 * q], a.x, v2); fma2(acc[2 * q + 1], a.y, v2);
        }
    }
    #pragma unroll
    for (int p = 0; p < 32; ++p) {
        float2 v = upk(acc[p]);
        int sc = (g << 6) + 2 * p;
        e_s[sc * TT2 + tc]       = fmaxf(v.x, 0.f);
        e_s[(sc + 1) * TT2 + tc] = fmaxf(v.y, 0.f);
    }

    // phase B: logits[g*64 .. g*64+63][tc], E2 streamed in 8 chunks of 32 input rows
    #pragma unroll
    for (int p = 0; p < 32; ++p) acc[p] = 0ull;
    for (int kk = 0; kk < SCD / RCD; ++kk) {
        __syncthreads();   // previous w_s readers (or phase A writers of e_s) done
        #pragma unroll 1
        for (int i = tid; i < RCD * NCLS; i += NT2) w_s[i] = g_e2[kk * RCD * NCLS + i];
        __syncthreads();
        #pragma unroll 2
        for (int c = 0; c < RCD; ++c) {
            u64 v2 = pk2(e_s[(kk * RCD + c) * TT2 + tc]);
            const ulonglong2* wr = (const ulonglong2*)(w_s + c * NCLS + (g << 6));
            #pragma unroll
            for (int q = 0; q < 16; ++q) {
                ulonglong2 a = wr[q];
                fma2(acc[2 * q], a.x, v2); fma2(acc[2 * q + 1], a.y, v2);
            }
        }
    }
    #pragma unroll
    for (int p = 0; p < 32; ++p) {
        float2 v = upk(acc[p]);
        int cls = (g << 6) + 2 * p;
        out[(b * NCLS + cls) * TD + t]       = v.x;
        out[(b * NCLS + cls + 1) * TD + t]   = v.y;
    }
}

// ---------------- launch ----------------
extern "C" void kernel_launch(void* const* d_in, const int* in_sizes, int n_in,
                              void* d_out, int out_size) {
    const float* x       = (const float*)d_in[0];
    const float* h       = (const float*)d_in[1];
    const float* start_w = (const float*)d_in[2];
    const float* dil_w   = (const float*)d_in[3];
    const float* f_w     = (const float*)d_in[4];
    const float* g_w     = (const float*)d_in[5];
    const float* cf_w    = (const float*)d_in[6];
    const float* cg_w    = (const float*)d_in[7];
    const float* out_w   = (const float*)d_in[8];
    const float* e1_w    = (const float*)d_in[9];
    const float* e2_w    = (const float*)d_in[10];
    float* out = (float*)d_out;

    cudaFuncSetAttribute(wn_main, cudaFuncAttributeMaxDynamicSharedMemorySize, SM1_BYTES);
    cudaFuncSetAttribute(wn_end,  cudaFuncAttributeMaxDynamicSharedMemorySize, SM2_BYTES);

    wn_pack<<<256, 256>>>(dil_w, f_w, g_w, cf_w, cg_w, out_w, e1_w, e2_w);
    wn_main<<<dim3(NTILES, BD), NT1, SM1_BYTES>>>(x, h, start_w);
    wn_end<<<dim3(TD / TT2, BD), NT2, SM2_BYTES>>>(out);
}